// round 3
// baseline (speedup 1.0000x reference)
#include <cuda_runtime.h>
#include <cuda_bf16.h>
#include <math_constants.h>

// Problem constants
#define NX 1024
#define NY 1024
#define DIM 128
#define DIM2 (DIM / 2)      // 64 packed f32x2 lanes per row
#define NCM1 4              // n_classes - 1

typedef unsigned long long u64;

// ---------------- scratch (no allocations allowed) ----------------
__device__ float g_S[NX * NY];               // s matrix, 4 MB (L2-resident)
__device__ float g_prow[32 * NX * 2];        // (max,sum) partial per (colchunk, row)
__device__ float g_pcol[8 * NY * 2];         // (max,sum) partial per (rowchunk, col)
__device__ float g_rowmax[NX];
__device__ float g_rowsuminv[NX];
__device__ float g_colmax[NY];
__device__ float g_colsuminv[NY];
__device__ float g_part[NX * 2];             // per-row partial (sum_a, sum_a*s)

// ---------------- packed f32x2 helpers ----------------
__device__ __forceinline__ u64 add2(u64 a, u64 b) {
    u64 r;
    asm("add.rn.f32x2 %0, %1, %2;" : "=l"(r) : "l"(a), "l"(b));
    return r;
}
// |x + yneg| where yneg already holds -y ; abs via sign-bit clear (ALU pipe)
__device__ __forceinline__ u64 absdiff2(u64 x, u64 yneg) {
    return add2(x, yneg) & 0x7FFFFFFF7FFFFFFFULL;
}

// ---------------- K1: s[i,j] = -sum_d |x[i,d] - y[j,d]| ----------------
// 32x32 tile per block, 256 threads (16x16), 2x2 outputs per thread.
// Full DIM staged once; smem [d2][row] as u64 pairs; Y staged pre-negated.
#define BI 32
#define BJ 32

__global__ __launch_bounds__(256) void k_s(const float* __restrict__ zx,
                                           const float* __restrict__ zy) {
    __shared__ u64 Xs[DIM2][BI + 1];
    __shared__ u64 Ys[DIM2][BJ + 1];

    const int tx = threadIdx.x;           // 0..15 -> j
    const int ty = threadIdx.y;           // 0..15 -> i
    const int tid = ty * 16 + tx;
    const int i0 = blockIdx.y * BI;
    const int j0 = blockIdx.x * BJ;

    const u64* zx2 = (const u64*)zx;
    const u64* zy2 = (const u64*)zy;

    // stage: 32 rows x 64 pairs per operand = 2048 u64 -> 8 per thread
    #pragma unroll
    for (int s = 0; s < 8; ++s) {
        int t = tid + s * 256;
        int d = t & (DIM2 - 1);
        int r = t >> 6;
        Xs[d][r] = zx2[(u64)(i0 + r) * DIM2 + d];
        Ys[d][r] = zy2[(u64)(j0 + r) * DIM2 + d] ^ 0x8000000080000000ULL; // pre-negate
    }
    __syncthreads();

    u64 acc00 = 0, acc01 = 0, acc10 = 0, acc11 = 0;

    #pragma unroll 16
    for (int d = 0; d < DIM2; ++d) {
        u64 x0 = Xs[d][ty];
        u64 x1 = Xs[d][ty + 16];
        u64 y0 = Ys[d][tx];
        u64 y1 = Ys[d][tx + 16];
        acc00 = add2(acc00, absdiff2(x0, y0));
        acc01 = add2(acc01, absdiff2(x0, y1));
        acc10 = add2(acc10, absdiff2(x1, y0));
        acc11 = add2(acc11, absdiff2(x1, y1));
    }

    float2 a00 = *(float2*)&acc00;
    float2 a01 = *(float2*)&acc01;
    float2 a10 = *(float2*)&acc10;
    float2 a11 = *(float2*)&acc11;

    g_S[(i0 + ty     ) * NY + j0 + tx     ] = -(a00.x + a00.y);
    g_S[(i0 + ty     ) * NY + j0 + tx + 16] = -(a01.x + a01.y);
    g_S[(i0 + ty + 16) * NY + j0 + tx     ] = -(a10.x + a10.y);
    g_S[(i0 + ty + 16) * NY + j0 + tx + 16] = -(a11.x + a11.y);
}

// ---------------- K2: fused row+col online-softmax partials ----------------
// grid (32 colgroups, 8 rowchunks), block (32,8).
// Block (bx,by): cols [bx*32,+32), rows [by*128,+128). Each thread holds 16 vals.
__global__ __launch_bounds__(256) void k_stats() {
    const int tx = threadIdx.x;       // col within group
    const int ty = threadIdx.y;       // row phase
    const int bx = blockIdx.x;
    const int by = blockIdx.y;
    const int j  = bx * 32 + tx;
    const int i0 = by * 128;

    float v[16];
    #pragma unroll
    for (int k = 0; k < 16; ++k)
        v[k] = g_S[(i0 + ty + 8 * k) * NY + j];

    __shared__ float sred[8][32];

    // ---- column partials: max then sum over the 128-row chunk ----
    float cm = v[0];
    #pragma unroll
    for (int k = 1; k < 16; ++k) cm = fmaxf(cm, v[k]);
    sred[ty][tx] = cm;
    __syncthreads();
    if (ty == 0) {
        float m = sred[0][tx];
        #pragma unroll
        for (int r = 1; r < 8; ++r) m = fmaxf(m, sred[r][tx]);
        sred[0][tx] = m;
    }
    __syncthreads();
    const float cmax_b = sred[0][tx];
    __syncthreads();

    float cs = 0.f;
    #pragma unroll
    for (int k = 0; k < 16; ++k) cs += __expf(v[k] - cmax_b);
    sred[ty][tx] = cs;
    __syncthreads();
    if (ty == 0) {
        float s = 0.f;
        #pragma unroll
        for (int r = 0; r < 8; ++r) s += sred[r][tx];
        g_pcol[(by * NY + j) * 2 + 0] = cmax_b;
        g_pcol[(by * NY + j) * 2 + 1] = s;
    }

    // ---- row partials: per k, warp reduce across the 32 cols ----
    #pragma unroll
    for (int k = 0; k < 16; ++k) {
        float m = v[k];
        #pragma unroll
        for (int o = 16; o > 0; o >>= 1)
            m = fmaxf(m, __shfl_xor_sync(0xffffffffu, m, o));
        float e = __expf(v[k] - m);
        #pragma unroll
        for (int o = 16; o > 0; o >>= 1)
            e += __shfl_xor_sync(0xffffffffu, e, o);
        if (tx == 0) {
            int i = i0 + ty + 8 * k;
            g_prow[(bx * NX + i) * 2 + 0] = m;
            g_prow[(bx * NX + i) * 2 + 1] = e;
        }
    }
}

// ---------------- K3: merge online-softmax partials (deterministic) ----------------
__global__ __launch_bounds__(256) void k_merge() {
    const int g = blockIdx.x * 256 + threadIdx.x;   // 0..2047
    if (g < NX) {
        const int i = g;
        float m = -CUDART_INF_F, s = 0.f;
        #pragma unroll 4
        for (int p = 0; p < 32; ++p) {
            float pm = g_prow[(p * NX + i) * 2 + 0];
            float ps = g_prow[(p * NX + i) * 2 + 1];
            if (pm > m) { s = s * __expf(m - pm) + ps; m = pm; }
            else        { s += ps * __expf(pm - m); }
        }
        g_rowmax[i] = m;
        g_rowsuminv[i] = 1.0f / s;
    } else {
        const int j = g - NX;
        float m = -CUDART_INF_F, s = 0.f;
        #pragma unroll
        for (int p = 0; p < 8; ++p) {
            float pm = g_pcol[(p * NY + j) * 2 + 0];
            float ps = g_pcol[(p * NY + j) * 2 + 1];
            if (pm > m) { s = s * __expf(m - pm) + ps; m = pm; }
            else        { s += ps * __expf(pm - m); }
        }
        g_colmax[j] = m;
        g_colsuminv[j] = 1.0f / s;
    }
}

// ---------------- K4: a = ea + eb - ea*eb; per-row partial (sum_a, sum_a*s) ----------------
__global__ __launch_bounds__(256) void k_comb() {
    const int i = blockIdx.x;
    const int t = threadIdx.x;
    const float rm = g_rowmax[i];
    const float ri = g_rowsuminv[i];

    float pa = 0.f, pas = 0.f;
    #pragma unroll
    for (int jj = 0; jj < NY / 256; ++jj) {
        int j = t + jj * 256;
        float s = g_S[i * NY + j];
        float ea = __expf(s - rm) * ri;
        float eb = __expf(s - g_colmax[j]) * g_colsuminv[j];
        float a = ea + eb - ea * eb;
        pa  += a;
        pas += a * s;
    }

    __shared__ float r1[256];
    __shared__ float r2[256];
    r1[t] = pa;
    r2[t] = pas;
    __syncthreads();
    for (int o = 128; o > 0; o >>= 1) {
        if (t < o) { r1[t] += r1[t + o]; r2[t] += r2[t + o]; }
        __syncthreads();
    }
    if (t == 0) {
        g_part[i * 2 + 0] = r1[0];
        g_part[i * 2 + 1] = r2[0];
    }
}

// ---------------- K5: final deterministic reduce + logits ----------------
__global__ __launch_bounds__(256) void k_final(const float* __restrict__ theta,
                                               const float* __restrict__ beta,
                                               float* __restrict__ out) {
    __shared__ float sa[256];
    __shared__ float sb[256];
    const int t = threadIdx.x;
    float a = 0.f, b = 0.f;
    #pragma unroll
    for (int i = t; i < NX; i += 256) {
        a += g_part[2 * i + 0];
        b += g_part[2 * i + 1];
    }
    sa[t] = a;
    sb[t] = b;
    __syncthreads();
    for (int o = 128; o > 0; o >>= 1) {
        if (t < o) { sa[t] += sa[t + o]; sb[t] += sb[t + o]; }
        __syncthreads();
    }
    if (t < NCM1) {
        float c = sb[0] / sa[0];
        out[t] = c * theta[t] + beta[t];
    }
}

// ---------------- launch (kernel launches only; graph-capture safe) ----------------
extern "C" void kernel_launch(void* const* d_in, const int* in_sizes, int n_in,
                              void* d_out, int out_size) {
    const float* zx    = (const float*)d_in[0];   // (1024,128)
    const float* zy    = (const float*)d_in[1];   // (1024,128)
    const float* theta = (const float*)d_in[2];   // (1,4)
    const float* beta  = (const float*)d_in[3];   // (4,)
    float* out = (float*)d_out;

    k_s<<<dim3(NY / BJ, NX / BI), dim3(16, 16)>>>(zx, zy);   // 1024 blocks
    k_stats<<<dim3(NY / 32, NX / 128), dim3(32, 8)>>>();     // 256 blocks
    k_merge<<<8, 256>>>();
    k_comb<<<NX, 256>>>();
    k_final<<<1, 256>>>(theta, beta, out);
}

// round 5
// speedup vs baseline: 1.1323x; 1.1323x over previous
#include <cuda_runtime.h>
#include <cuda_bf16.h>
#include <math_constants.h>

// Problem constants
#define NX 1024
#define NY 1024
#define DIM 128
#define DIM2 (DIM / 2)      // 64 packed f32x2 lanes per row
#define NCM1 4              // n_classes - 1

typedef unsigned long long u64;

// ---------------- scratch (no allocations allowed) ----------------
__device__ float g_S[NX * NY];               // s matrix, 4 MB (L2-resident)
__device__ float g_prow[32 * NX * 2];        // (max,sum) per (tileJ, row)
__device__ float g_pcol[32 * NY * 2];        // (max,sum) per (tileI, col)
__device__ float g_rowmax[NX];
__device__ float g_rowsuminv[NX];
__device__ float g_colmax[NY];
__device__ float g_colsuminv[NY];
__device__ float g_part[NX * 2];             // per-row partial (sum_a, sum_a*s)

// ---------------- packed f32x2 helpers ----------------
__device__ __forceinline__ u64 add2(u64 a, u64 b) {
    u64 r;
    asm("add.rn.f32x2 %0, %1, %2;" : "=l"(r) : "l"(a), "l"(b));
    return r;
}
// |x + yneg| where yneg already holds -y ; abs via sign-bit clear (ALU pipe)
__device__ __forceinline__ u64 absdiff2(u64 x, u64 yneg) {
    return add2(x, yneg) & 0x7FFFFFFF7FFFFFFFULL;
}

// ---------------- K1: S tile + fused row/col softmax partials ----------------
// 32x32 tile per block, 256 threads (16x16), 2x2 outputs per thread.
// Full DIM staged once; smem [d2][row] as u64 pairs; Y staged pre-negated.
// Epilogue: per-tile row (max,sumexp) via half-warp shuffles,
//           per-tile col (max,sumexp) via smem reduction.
#define BI 32
#define BJ 32

__global__ __launch_bounds__(256) void k_s(const float* __restrict__ zx,
                                           const float* __restrict__ zy) {
    __shared__ u64 Xs[DIM2][BI + 1];
    __shared__ u64 Ys[DIM2][BJ + 1];
    __shared__ float cred[16][33];
    __shared__ float cmaxs[32];

    const int tx = threadIdx.x;           // 0..15 -> j
    const int ty = threadIdx.y;           // 0..15 -> i
    const int tid = ty * 16 + tx;
    const int bx = blockIdx.x;            // tileJ
    const int by = blockIdx.y;            // tileI
    const int i0 = by * BI;
    const int j0 = bx * BJ;

    const u64* zx2 = (const u64*)zx;
    const u64* zy2 = (const u64*)zy;

    // stage: 32 rows x 64 pairs per operand = 2048 u64 -> 8 per thread
    #pragma unroll
    for (int s = 0; s < 8; ++s) {
        int t = tid + s * 256;
        int d = t & (DIM2 - 1);
        int r = t >> 6;
        Xs[d][r] = zx2[(u64)(i0 + r) * DIM2 + d];
        Ys[d][r] = zy2[(u64)(j0 + r) * DIM2 + d] ^ 0x8000000080000000ULL; // pre-negate
    }
    __syncthreads();

    u64 acc00 = 0, acc01 = 0, acc10 = 0, acc11 = 0;

    #pragma unroll 16
    for (int d = 0; d < DIM2; ++d) {
        u64 x0 = Xs[d][ty];
        u64 x1 = Xs[d][ty + 16];
        u64 y0 = Ys[d][tx];
        u64 y1 = Ys[d][tx + 16];
        acc00 = add2(acc00, absdiff2(x0, y0));
        acc01 = add2(acc01, absdiff2(x0, y1));
        acc10 = add2(acc10, absdiff2(x1, y0));
        acc11 = add2(acc11, absdiff2(x1, y1));
    }

    float2 a00 = *(float2*)&acc00;
    float2 a01 = *(float2*)&acc01;
    float2 a10 = *(float2*)&acc10;
    float2 a11 = *(float2*)&acc11;

    const float s00 = -(a00.x + a00.y);   // (i0+ty     , j0+tx     )
    const float s01 = -(a01.x + a01.y);   // (i0+ty     , j0+tx+16  )
    const float s10 = -(a10.x + a10.y);   // (i0+ty+16  , j0+tx     )
    const float s11 = -(a11.x + a11.y);   // (i0+ty+16  , j0+tx+16  )

    g_S[(i0 + ty     ) * NY + j0 + tx     ] = s00;
    g_S[(i0 + ty     ) * NY + j0 + tx + 16] = s01;
    g_S[(i0 + ty + 16) * NY + j0 + tx     ] = s10;
    g_S[(i0 + ty + 16) * NY + j0 + tx + 16] = s11;

    // ---- row partials: 16 threads sharing ty are one half-warp ----
    const unsigned FULL = 0xffffffffu;
    float m0 = fmaxf(s00, s01);
    float m1 = fmaxf(s10, s11);
    #pragma unroll
    for (int o = 8; o > 0; o >>= 1) {
        m0 = fmaxf(m0, __shfl_xor_sync(FULL, m0, o));
        m1 = fmaxf(m1, __shfl_xor_sync(FULL, m1, o));
    }
    float e0 = __expf(s00 - m0) + __expf(s01 - m0);
    float e1 = __expf(s10 - m1) + __expf(s11 - m1);
    #pragma unroll
    for (int o = 8; o > 0; o >>= 1) {
        e0 += __shfl_xor_sync(FULL, e0, o);
        e1 += __shfl_xor_sync(FULL, e1, o);
    }
    if (tx == 0) {
        g_prow[(bx * NX + i0 + ty     ) * 2 + 0] = m0;
        g_prow[(bx * NX + i0 + ty     ) * 2 + 1] = e0;
        g_prow[(bx * NX + i0 + ty + 16) * 2 + 0] = m1;
        g_prow[(bx * NX + i0 + ty + 16) * 2 + 1] = e1;
    }

    // ---- col partials via smem ----
    cred[ty][tx     ] = fmaxf(s00, s10);
    cred[ty][tx + 16] = fmaxf(s01, s11);
    __syncthreads();
    if (tid < 32) {
        float m = cred[0][tid];
        #pragma unroll
        for (int r = 1; r < 16; ++r) m = fmaxf(m, cred[r][tid]);
        cmaxs[tid] = m;
    }
    __syncthreads();
    {
        const float cm0 = cmaxs[tx];
        const float cm1 = cmaxs[tx + 16];
        cred[ty][tx     ] = __expf(s00 - cm0) + __expf(s10 - cm0);
        cred[ty][tx + 16] = __expf(s01 - cm1) + __expf(s11 - cm1);
    }
    __syncthreads();
    if (tid < 32) {
        float s = 0.f;
        #pragma unroll
        for (int r = 0; r < 16; ++r) s += cred[r][tid];
        g_pcol[(by * NY + j0 + tid) * 2 + 0] = cmaxs[tid];
        g_pcol[(by * NY + j0 + tid) * 2 + 1] = s;
    }
}

// ---------------- K2: merge online-softmax partials (deterministic) ----------------
__global__ __launch_bounds__(256) void k_merge() {
    const int g = blockIdx.x * 256 + threadIdx.x;   // 0..2047
    if (g < NX) {
        const int i = g;
        float m = -CUDART_INF_F, s = 0.f;
        #pragma unroll 4
        for (int p = 0; p < 32; ++p) {
            float pm = g_prow[(p * NX + i) * 2 + 0];
            float ps = g_prow[(p * NX + i) * 2 + 1];
            if (pm > m) { s = s * __expf(m - pm) + ps; m = pm; }
            else        { s += ps * __expf(pm - m); }
        }
        g_rowmax[i] = m;
        g_rowsuminv[i] = 1.0f / s;
    } else {
        const int j = g - NX;
        float m = -CUDART_INF_F, s = 0.f;
        #pragma unroll 4
        for (int p = 0; p < 32; ++p) {
            float pm = g_pcol[(p * NY + j) * 2 + 0];
            float ps = g_pcol[(p * NY + j) * 2 + 1];
            if (pm > m) { s = s * __expf(m - pm) + ps; m = pm; }
            else        { s += ps * __expf(pm - m); }
        }
        g_colmax[j] = m;
        g_colsuminv[j] = 1.0f / s;
    }
}

// ---------------- K3: a = ea + eb - ea*eb; per-row partial (sum_a, sum_a*s) ----------------
// 1024 blocks x 128 threads; 8 elems/thread via two float4 loads (full ILP).
__global__ __launch_bounds__(128) void k_comb() {
    const int i = blockIdx.x;
    const int t = threadIdx.x;
    const float rm = g_rowmax[i];
    const float ri = g_rowsuminv[i];

    const float4* S4  = (const float4*)(g_S + i * NY);
    const float4* cm4 = (const float4*)g_colmax;
    const float4* ci4 = (const float4*)g_colsuminv;

    float pa = 0.f, pas = 0.f;
    #pragma unroll
    for (int kk = 0; kk < 2; ++kk) {
        const int idx = t + kk * 128;
        const float4 s  = S4[idx];
        const float4 cm = cm4[idx];
        const float4 ci = ci4[idx];

        float ea, eb, a;
        ea = __expf(s.x - rm) * ri; eb = __expf(s.x - cm.x) * ci.x;
        a = ea + eb - ea * eb; pa += a; pas += a * s.x;
        ea = __expf(s.y - rm) * ri; eb = __expf(s.y - cm.y) * ci.y;
        a = ea + eb - ea * eb; pa += a; pas += a * s.y;
        ea = __expf(s.z - rm) * ri; eb = __expf(s.z - cm.z) * ci.z;
        a = ea + eb - ea * eb; pa += a; pas += a * s.z;
        ea = __expf(s.w - rm) * ri; eb = __expf(s.w - cm.w) * ci.w;
        a = ea + eb - ea * eb; pa += a; pas += a * s.w;
    }

    const unsigned FULL = 0xffffffffu;
    #pragma unroll
    for (int o = 16; o > 0; o >>= 1) {
        pa  += __shfl_xor_sync(FULL, pa,  o);
        pas += __shfl_xor_sync(FULL, pas, o);
    }

    __shared__ float sa[4];
    __shared__ float sb[4];
    const int wid = t >> 5;
    if ((t & 31) == 0) { sa[wid] = pa; sb[wid] = pas; }
    __syncthreads();
    if (t == 0) {
        g_part[i * 2 + 0] = (sa[0] + sa[1]) + (sa[2] + sa[3]);
        g_part[i * 2 + 1] = (sb[0] + sb[1]) + (sb[2] + sb[3]);
    }
}

// ---------------- K4: final deterministic reduce + logits ----------------
__global__ __launch_bounds__(256) void k_final(const float* __restrict__ theta,
                                               const float* __restrict__ beta,
                                               float* __restrict__ out) {
    __shared__ float sa[256];
    __shared__ float sb[256];
    const int t = threadIdx.x;
    float a = 0.f, b = 0.f;
    #pragma unroll
    for (int i = t; i < NX; i += 256) {
        a += g_part[2 * i + 0];
        b += g_part[2 * i + 1];
    }
    sa[t] = a;
    sb[t] = b;
    __syncthreads();
    for (int o = 128; o > 0; o >>= 1) {
        if (t < o) { sa[t] += sa[t + o]; sb[t] += sb[t + o]; }
        __syncthreads();
    }
    if (t < NCM1) {
        float c = sb[0] / sa[0];
        out[t] = c * theta[t] + beta[t];
    }
}

// ---------------- launch (kernel launches only; graph-capture safe) ----------------
extern "C" void kernel_launch(void* const* d_in, const int* in_sizes, int n_in,
                              void* d_out, int out_size) {
    const float* zx    = (const float*)d_in[0];   // (1024,128)
    const float* zy    = (const float*)d_in[1];   // (1024,128)
    const float* theta = (const float*)d_in[2];   // (1,4)
    const float* beta  = (const float*)d_in[3];   // (4,)
    float* out = (float*)d_out;

    k_s<<<dim3(NY / BJ, NX / BI), dim3(16, 16)>>>(zx, zy);   // 1024 blocks
    k_merge<<<8, 256>>>();
    k_comb<<<NX, 128>>>();
    k_final<<<1, 256>>>(theta, beta, out);
}

// round 6
// speedup vs baseline: 1.3034x; 1.1511x over previous
#include <cuda_runtime.h>
#include <cuda_bf16.h>
#include <math_constants.h>

// Problem constants
#define NX 1024
#define NY 1024
#define DIM 128
#define DIM2 (DIM / 2)      // 64 packed f32x2 lanes per row
#define NCM1 4              // n_classes - 1

typedef unsigned long long u64;

// ---------------- scratch (no allocations allowed) ----------------
__device__ float g_S[NX * NY];               // s matrix, 4 MB (L2-resident)
__device__ float g_prow[32 * NX * 2];        // (max,sum) per (tileJ, row)
__device__ float g_pcol[32 * NY * 2];        // (max,sum) per (tileI, col)
__device__ float g_rowmax[NX];
__device__ float g_rowsuminv[NX];
__device__ float g_colmax[NY];
__device__ float g_colsuminv[NY];
__device__ float g_part[NX * 2];             // per-row partial (sum_a, sum_a*s)
__device__ int   g_rowctr[32];               // per row-strip arrival counters
__device__ int   g_colctr[32];               // per col-strip arrival counters
__device__ int   g_combctr;                  // k_comb arrival counter

// ---------------- packed f32x2 helpers ----------------
__device__ __forceinline__ u64 add2(u64 a, u64 b) {
    u64 r;
    asm("add.rn.f32x2 %0, %1, %2;" : "=l"(r) : "l"(a), "l"(b));
    return r;
}
// |x + yneg| where yneg already holds -y ; abs via sign-bit clear (ALU pipe)
__device__ __forceinline__ u64 absdiff2(u64 x, u64 yneg) {
    return add2(x, yneg) & 0x7FFFFFFF7FFFFFFFULL;
}

// ---------------- K1: S tile + fused partials + distributed strip merge ----------------
#define BI 32
#define BJ 32

__global__ __launch_bounds__(256) void k_s(const float* __restrict__ zx,
                                           const float* __restrict__ zy) {
    __shared__ u64 Xs[DIM2][BI + 1];
    __shared__ u64 Ys[DIM2][BJ + 1];
    __shared__ float cred[16][33];
    __shared__ float cmaxs[32];
    __shared__ int lastRow, lastCol;

    const int tx = threadIdx.x;           // 0..15 -> j
    const int ty = threadIdx.y;           // 0..15 -> i
    const int tid = ty * 16 + tx;
    const int bx = blockIdx.x;            // tileJ
    const int by = blockIdx.y;            // tileI
    const int i0 = by * BI;
    const int j0 = bx * BJ;

    const u64* zx2 = (const u64*)zx;
    const u64* zy2 = (const u64*)zy;

    #pragma unroll
    for (int s = 0; s < 8; ++s) {
        int t = tid + s * 256;
        int d = t & (DIM2 - 1);
        int r = t >> 6;
        Xs[d][r] = zx2[(u64)(i0 + r) * DIM2 + d];
        Ys[d][r] = zy2[(u64)(j0 + r) * DIM2 + d] ^ 0x8000000080000000ULL; // pre-negate
    }
    __syncthreads();

    u64 acc00 = 0, acc01 = 0, acc10 = 0, acc11 = 0;

    #pragma unroll 16
    for (int d = 0; d < DIM2; ++d) {
        u64 x0 = Xs[d][ty];
        u64 x1 = Xs[d][ty + 16];
        u64 y0 = Ys[d][tx];
        u64 y1 = Ys[d][tx + 16];
        acc00 = add2(acc00, absdiff2(x0, y0));
        acc01 = add2(acc01, absdiff2(x0, y1));
        acc10 = add2(acc10, absdiff2(x1, y0));
        acc11 = add2(acc11, absdiff2(x1, y1));
    }

    float2 a00 = *(float2*)&acc00;
    float2 a01 = *(float2*)&acc01;
    float2 a10 = *(float2*)&acc10;
    float2 a11 = *(float2*)&acc11;

    const float s00 = -(a00.x + a00.y);
    const float s01 = -(a01.x + a01.y);
    const float s10 = -(a10.x + a10.y);
    const float s11 = -(a11.x + a11.y);

    g_S[(i0 + ty     ) * NY + j0 + tx     ] = s00;
    g_S[(i0 + ty     ) * NY + j0 + tx + 16] = s01;
    g_S[(i0 + ty + 16) * NY + j0 + tx     ] = s10;
    g_S[(i0 + ty + 16) * NY + j0 + tx + 16] = s11;

    // ---- row partials: 16 threads sharing ty are one half-warp ----
    const unsigned FULL = 0xffffffffu;
    float m0 = fmaxf(s00, s01);
    float m1 = fmaxf(s10, s11);
    #pragma unroll
    for (int o = 8; o > 0; o >>= 1) {
        m0 = fmaxf(m0, __shfl_xor_sync(FULL, m0, o));
        m1 = fmaxf(m1, __shfl_xor_sync(FULL, m1, o));
    }
    float e0 = __expf(s00 - m0) + __expf(s01 - m0);
    float e1 = __expf(s10 - m1) + __expf(s11 - m1);
    #pragma unroll
    for (int o = 8; o > 0; o >>= 1) {
        e0 += __shfl_xor_sync(FULL, e0, o);
        e1 += __shfl_xor_sync(FULL, e1, o);
    }
    if (tx == 0) {
        g_prow[(bx * NX + i0 + ty     ) * 2 + 0] = m0;
        g_prow[(bx * NX + i0 + ty     ) * 2 + 1] = e0;
        g_prow[(bx * NX + i0 + ty + 16) * 2 + 0] = m1;
        g_prow[(bx * NX + i0 + ty + 16) * 2 + 1] = e1;
    }

    // ---- col partials via smem ----
    cred[ty][tx     ] = fmaxf(s00, s10);
    cred[ty][tx + 16] = fmaxf(s01, s11);
    __syncthreads();
    if (tid < 32) {
        float m = cred[0][tid];
        #pragma unroll
        for (int r = 1; r < 16; ++r) m = fmaxf(m, cred[r][tid]);
        cmaxs[tid] = m;
    }
    __syncthreads();
    {
        const float cm0 = cmaxs[tx];
        const float cm1 = cmaxs[tx + 16];
        cred[ty][tx     ] = __expf(s00 - cm0) + __expf(s10 - cm0);
        cred[ty][tx + 16] = __expf(s01 - cm1) + __expf(s11 - cm1);
    }
    __syncthreads();
    if (tid < 32) {
        float s = 0.f;
        #pragma unroll
        for (int r = 0; r < 16; ++r) s += cred[r][tid];
        g_pcol[(by * NY + j0 + tid) * 2 + 0] = cmaxs[tid];
        g_pcol[(by * NY + j0 + tid) * 2 + 1] = s;
    }

    // ---- strip arrival: last block in each strip merges that strip ----
    if (tid == 0) {
        __threadfence();
        lastRow = (atomicAdd(&g_rowctr[by], 1) == 31);
        lastCol = (atomicAdd(&g_colctr[bx], 1) == 31);
    }
    __syncthreads();

    if (lastRow) {
        // warp 0: thread t merges row i0+t over 32 partials (fixed order)
        if (tid < 32) {
            const int i = i0 + tid;
            float m = -CUDART_INF_F;
            #pragma unroll
            for (int p = 0; p < 32; ++p)
                m = fmaxf(m, g_prow[(p * NX + i) * 2 + 0]);
            float s = 0.f;
            #pragma unroll
            for (int p = 0; p < 32; ++p)
                s += g_prow[(p * NX + i) * 2 + 1] * __expf(g_prow[(p * NX + i) * 2 + 0] - m);
            g_rowmax[i] = m;
            g_rowsuminv[i] = 1.0f / s;
        }
        if (tid == 0) g_rowctr[by] = 0;   // reset for graph replay
    }
    if (lastCol) {
        // warp 7: thread (tid-224) merges col j0+(tid-224)
        if (tid >= 224) {
            const int j = j0 + (tid - 224);
            float m = -CUDART_INF_F;
            #pragma unroll
            for (int p = 0; p < 32; ++p)
                m = fmaxf(m, g_pcol[(p * NY + j) * 2 + 0]);
            float s = 0.f;
            #pragma unroll
            for (int p = 0; p < 32; ++p)
                s += g_pcol[(p * NY + j) * 2 + 1] * __expf(g_pcol[(p * NY + j) * 2 + 0] - m);
            g_colmax[j] = m;
            g_colsuminv[j] = 1.0f / s;
        }
        if (tid == 224) g_colctr[bx] = 0; // reset for graph replay
    }
}

// ---------------- K2: combine + per-row partials + last-block logits ----------------
// 1024 blocks x 128 threads; 8 elems/thread via two float4 loads (full ILP).
__global__ __launch_bounds__(128) void k_comb(const float* __restrict__ theta,
                                              const float* __restrict__ beta,
                                              float* __restrict__ out) {
    const int i = blockIdx.x;
    const int t = threadIdx.x;
    const float rm = g_rowmax[i];
    const float ri = g_rowsuminv[i];

    const float4* S4  = (const float4*)(g_S + i * NY);
    const float4* cm4 = (const float4*)g_colmax;
    const float4* ci4 = (const float4*)g_colsuminv;

    float pa = 0.f, pas = 0.f;
    #pragma unroll
    for (int kk = 0; kk < 2; ++kk) {
        const int idx = t + kk * 128;
        const float4 s  = S4[idx];
        const float4 cm = cm4[idx];
        const float4 ci = ci4[idx];

        float ea, eb, a;
        ea = __expf(s.x - rm) * ri; eb = __expf(s.x - cm.x) * ci.x;
        a = ea + eb - ea * eb; pa += a; pas += a * s.x;
        ea = __expf(s.y - rm) * ri; eb = __expf(s.y - cm.y) * ci.y;
        a = ea + eb - ea * eb; pa += a; pas += a * s.y;
        ea = __expf(s.z - rm) * ri; eb = __expf(s.z - cm.z) * ci.z;
        a = ea + eb - ea * eb; pa += a; pas += a * s.z;
        ea = __expf(s.w - rm) * ri; eb = __expf(s.w - cm.w) * ci.w;
        a = ea + eb - ea * eb; pa += a; pas += a * s.w;
    }

    const unsigned FULL = 0xffffffffu;
    #pragma unroll
    for (int o = 16; o > 0; o >>= 1) {
        pa  += __shfl_xor_sync(FULL, pa,  o);
        pas += __shfl_xor_sync(FULL, pas, o);
    }

    __shared__ float sa[4];
    __shared__ float sb[4];
    __shared__ int last;
    const int wid = t >> 5;
    if ((t & 31) == 0) { sa[wid] = pa; sb[wid] = pas; }
    __syncthreads();
    if (t == 0) {
        g_part[i * 2 + 0] = (sa[0] + sa[1]) + (sa[2] + sa[3]);
        g_part[i * 2 + 1] = (sb[0] + sb[1]) + (sb[2] + sb[3]);
        __threadfence();
        last = (atomicAdd(&g_combctr, 1) == NX - 1);
    }
    __syncthreads();

    if (last) {
        // final deterministic reduce + logits, inside the last block
        float a = 0.f, b = 0.f;
        #pragma unroll
        for (int r = t; r < NX; r += 128) {
            a += g_part[2 * r + 0];
            b += g_part[2 * r + 1];
        }
        #pragma unroll
        for (int o = 16; o > 0; o >>= 1) {
            a += __shfl_xor_sync(FULL, a, o);
            b += __shfl_xor_sync(FULL, b, o);
        }
        if ((t & 31) == 0) { sa[wid] = a; sb[wid] = b; }
        __syncthreads();
        if (t < NCM1) {
            float fa = (sa[0] + sa[1]) + (sa[2] + sa[3]);
            float fb = (sb[0] + sb[1]) + (sb[2] + sb[3]);
            float c = fb / fa;
            out[t] = c * theta[t] + beta[t];
        }
        if (t == 0) g_combctr = 0;    // reset for graph replay
    }
}

// ---------------- launch (2 kernels only; graph-capture safe) ----------------
extern "C" void kernel_launch(void* const* d_in, const int* in_sizes, int n_in,
                              void* d_out, int out_size) {
    const float* zx    = (const float*)d_in[0];   // (1024,128)
    const float* zy    = (const float*)d_in[1];   // (1024,128)
    const float* theta = (const float*)d_in[2];   // (1,4)
    const float* beta  = (const float*)d_in[3];   // (4,)
    float* out = (float*)d_out;

    k_s<<<dim3(NY / BJ, NX / BI), dim3(16, 16)>>>(zx, zy);   // 1024 blocks
    k_comb<<<NX, 128>>>(theta, beta, out);                   // 1024 blocks
}